// round 1
// baseline (speedup 1.0000x reference)
#include <cuda_runtime.h>
#include <cuda_bf16.h>
#include <math.h>

// Problem constants (fixed by setup_inputs)
#define BB   4
#define LL   1024
#define EE   1024
#define HH   16
#define DD   64
#define WW   128
#define NT   (BB*LL)          // 4096 rows
#define E3   (3*EE)
#define E4   (4*EE)

#define QT   32               // queries per attention block
#define BAND (QT + 2*WW)      // 288
#define DP   (DD + 1)         // padded row stride for Q/K/V smem (odd -> conflict free)

// ---------------- scratch (device globals; no allocation allowed) -------------
__device__ float g_qkv[NT * E3];          // 50 MB
__device__ float g_ctx[NT * EE];          // 16.8 MB
__device__ float g_s1 [NT * EE];          // x + attn_out
__device__ float g_h  [NT * EE];          // LN1 output
__device__ float g_ff [NT * E4];          // 67 MB
__device__ float g_s2 [NT * EE];          // h + ff
__device__ float g_P  [BB * HH * LL * BAND];  // 75.5 MB band-packed probs

// =====================================================================
// GEMM:  C[M,N] = A[M,K] * W[N,K]^T + bias[N] (+ res[M,N]) (relu optional)
// 128x128 block tile, BK=16, 256 threads, 8x8 per thread.
// =====================================================================
#define BM 128
#define BN 128
#define BK 16
#define SPAD 4

__global__ __launch_bounds__(256, 2)
void gemm_tn(const float* __restrict__ A, const float* __restrict__ W,
             const float* __restrict__ bias, const float* __restrict__ res,
             float* __restrict__ C, int M, int N, int K, int relu)
{
    __shared__ float As[BK][BM + SPAD];
    __shared__ float Bs[BK][BN + SPAD];

    const int t  = threadIdx.x;
    const int tx = t & 15;          // 0..15  (cols)
    const int ty = t >> 4;          // 0..15  (rows)
    const int m0 = blockIdx.y * BM;
    const int n0 = blockIdx.x * BN;

    const int lrow = t >> 2;        // 0..63
    const int lk4  = (t & 3) * 4;   // 0,4,8,12

    float acc[8][8];
#pragma unroll
    for (int i = 0; i < 8; i++)
#pragma unroll
        for (int j = 0; j < 8; j++) acc[i][j] = 0.f;

    for (int k0 = 0; k0 < K; k0 += BK) {
        const float4 av0 = *(const float4*)&A[(size_t)(m0 + lrow)      * K + k0 + lk4];
        const float4 av1 = *(const float4*)&A[(size_t)(m0 + lrow + 64) * K + k0 + lk4];
        const float4 bv0 = *(const float4*)&W[(size_t)(n0 + lrow)      * K + k0 + lk4];
        const float4 bv1 = *(const float4*)&W[(size_t)(n0 + lrow + 64) * K + k0 + lk4];
        __syncthreads();
        As[lk4 + 0][lrow] = av0.x; As[lk4 + 1][lrow] = av0.y;
        As[lk4 + 2][lrow] = av0.z; As[lk4 + 3][lrow] = av0.w;
        As[lk4 + 0][lrow + 64] = av1.x; As[lk4 + 1][lrow + 64] = av1.y;
        As[lk4 + 2][lrow + 64] = av1.z; As[lk4 + 3][lrow + 64] = av1.w;
        Bs[lk4 + 0][lrow] = bv0.x; Bs[lk4 + 1][lrow] = bv0.y;
        Bs[lk4 + 2][lrow] = bv0.z; Bs[lk4 + 3][lrow] = bv0.w;
        Bs[lk4 + 0][lrow + 64] = bv1.x; Bs[lk4 + 1][lrow + 64] = bv1.y;
        Bs[lk4 + 2][lrow + 64] = bv1.z; Bs[lk4 + 3][lrow + 64] = bv1.w;
        __syncthreads();

#pragma unroll
        for (int kk = 0; kk < BK; kk++) {
            float4 a0 = *(const float4*)&As[kk][ty * 8];
            float4 a1 = *(const float4*)&As[kk][ty * 8 + 4];
            float4 b0 = *(const float4*)&Bs[kk][tx * 8];
            float4 b1 = *(const float4*)&Bs[kk][tx * 8 + 4];
            float a[8] = {a0.x, a0.y, a0.z, a0.w, a1.x, a1.y, a1.z, a1.w};
            float b[8] = {b0.x, b0.y, b0.z, b0.w, b1.x, b1.y, b1.z, b1.w};
#pragma unroll
            for (int i = 0; i < 8; i++)
#pragma unroll
                for (int j = 0; j < 8; j++)
                    acc[i][j] = fmaf(a[i], b[j], acc[i][j]);
        }
    }

    // epilogue
    const float4 bz0 = *(const float4*)&bias[n0 + tx * 8];
    const float4 bz1 = *(const float4*)&bias[n0 + tx * 8 + 4];
    const float bvec[8] = {bz0.x, bz0.y, bz0.z, bz0.w, bz1.x, bz1.y, bz1.z, bz1.w};
#pragma unroll
    for (int i = 0; i < 8; i++) {
        const int m = m0 + ty * 8 + i;
        float v[8];
#pragma unroll
        for (int j = 0; j < 8; j++) v[j] = acc[i][j] + bvec[j];
        if (res) {
            const float4 r0 = *(const float4*)&res[(size_t)m * N + n0 + tx * 8];
            const float4 r1 = *(const float4*)&res[(size_t)m * N + n0 + tx * 8 + 4];
            v[0] += r0.x; v[1] += r0.y; v[2] += r0.z; v[3] += r0.w;
            v[4] += r1.x; v[5] += r1.y; v[6] += r1.z; v[7] += r1.w;
        }
        if (relu) {
#pragma unroll
            for (int j = 0; j < 8; j++) v[j] = fmaxf(v[j], 0.f);
        }
        *(float4*)&C[(size_t)m * N + n0 + tx * 8]     = make_float4(v[0], v[1], v[2], v[3]);
        *(float4*)&C[(size_t)m * N + n0 + tx * 8 + 4] = make_float4(v[4], v[5], v[6], v[7]);
    }
}

// =====================================================================
// Banded attention: one block per (b, head, 32-query tile).
// Full band (288 keys) in smem -> exact softmax, then P@V.
// Writes ctx and band-packed P (for head-mean reduction).
// =====================================================================
__global__ __launch_bounds__(256, 1)
void attn_kernel(const float* __restrict__ qkv)
{
    extern __shared__ float sm[];
    float* sQ = sm;                         // QT * DP
    float* sK = sQ + QT * DP;               // BAND * DP
    float* sV = sK + BAND * DP;             // BAND * DP
    float* sS = sV + BAND * DP;             // QT * BAND

    const int t  = threadIdx.x;
    const int qtile = blockIdx.x;
    const int h  = blockIdx.y;
    const int b  = blockIdx.z;
    const int q0 = qtile * QT;
    const int j0 = q0 - WW;

    // ---- load Q (32 x 64) ----
    for (int idx = t; idx < QT * 16; idx += 256) {
        const int row = idx >> 4, c4 = (idx & 15) * 4;
        const float4 q4 = *(const float4*)&qkv[(size_t)(b * LL + q0 + row) * E3 + h * DD + c4];
        float* d = &sQ[row * DP + c4];
        d[0] = q4.x; d[1] = q4.y; d[2] = q4.z; d[3] = q4.w;
    }
    // ---- load K, V band (288 x 64), zero-fill out of range ----
    for (int idx = t; idx < BAND * 16; idx += 256) {
        const int row = idx >> 4, c4 = (idx & 15) * 4;
        const int j = j0 + row;
        float4 k4 = make_float4(0.f, 0.f, 0.f, 0.f);
        float4 v4 = k4;
        if (j >= 0 && j < LL) {
            const float* kp = &qkv[(size_t)(b * LL + j) * E3 + EE + h * DD + c4];
            k4 = *(const float4*)kp;
            v4 = *(const float4*)(kp + EE);
        }
        float* kd = &sK[row * DP + c4];
        kd[0] = k4.x; kd[1] = k4.y; kd[2] = k4.z; kd[3] = k4.w;
        float* vd = &sV[row * DP + c4];
        vd[0] = v4.x; vd[1] = v4.y; vd[2] = v4.z; vd[3] = v4.w;
    }
    __syncthreads();

    const int tx = t & 31;   // 0..31
    const int ty = t >> 5;   // 0..7

    // ---- S = Q K^T * 1/8, masked.  thread: 4 rows x 9 cols ----
    float accS[4][9];
#pragma unroll
    for (int r = 0; r < 4; r++)
#pragma unroll
        for (int c = 0; c < 9; c++) accS[r][c] = 0.f;

#pragma unroll 4
    for (int d = 0; d < DD; d++) {
        float q[4];
#pragma unroll
        for (int r = 0; r < 4; r++) q[r] = sQ[(ty + 8 * r) * DP + d];
#pragma unroll
        for (int c = 0; c < 9; c++) {
            const float kv = sK[(tx + 32 * c) * DP + d];
#pragma unroll
            for (int r = 0; r < 4; r++) accS[r][c] = fmaf(q[r], kv, accS[r][c]);
        }
    }
#pragma unroll
    for (int r = 0; r < 4; r++) {
        const int qi = ty + 8 * r;
#pragma unroll
        for (int c = 0; c < 9; c++) {
            const int jj = tx + 32 * c;
            const int j = j0 + jj;
            const bool valid = (jj >= qi) && (jj <= qi + 2 * WW) && (j >= 0) && (j < LL);
            sS[qi * BAND + jj] = valid ? accS[r][c] * 0.125f : -1e30f;
        }
    }
    __syncthreads();

    // ---- softmax: warp w handles rows 4w..4w+3 ----
    {
        const int w = ty, lane = tx;
#pragma unroll
        for (int r = 0; r < 4; r++) {
            const int row = w * 4 + r;
            float vals[9];
            float mx = -1e30f;
#pragma unroll
            for (int c = 0; c < 9; c++) {
                vals[c] = sS[row * BAND + lane + 32 * c];
                mx = fmaxf(mx, vals[c]);
            }
#pragma unroll
            for (int off = 16; off > 0; off >>= 1)
                mx = fmaxf(mx, __shfl_xor_sync(0xffffffffu, mx, off));
            float s = 0.f;
#pragma unroll
            for (int c = 0; c < 9; c++) { vals[c] = __expf(vals[c] - mx); s += vals[c]; }
#pragma unroll
            for (int off = 16; off > 0; off >>= 1)
                s += __shfl_xor_sync(0xffffffffu, s, off);
            const float inv = 1.f / s;
#pragma unroll
            for (int c = 0; c < 9; c++)
                sS[row * BAND + lane + 32 * c] = vals[c] * inv;
        }
    }
    __syncthreads();

    // ---- ctx = P @ V. thread: 4 rows x 2 d-cols ----
    float accO[4][2];
#pragma unroll
    for (int r = 0; r < 4; r++) { accO[r][0] = 0.f; accO[r][1] = 0.f; }
#pragma unroll 4
    for (int jj = 0; jj < BAND; jj++) {
        const float v0 = sV[jj * DP + tx];
        const float v1 = sV[jj * DP + tx + 32];
#pragma unroll
        for (int r = 0; r < 4; r++) {
            const float p = sS[(ty + 8 * r) * BAND + jj];
            accO[r][0] = fmaf(p, v0, accO[r][0]);
            accO[r][1] = fmaf(p, v1, accO[r][1]);
        }
    }
#pragma unroll
    for (int r = 0; r < 4; r++) {
        const int qi = ty + 8 * r;
        float* cp = &g_ctx[(size_t)(b * LL + q0 + qi) * EE + h * DD + tx];
        cp[0]  = accO[r][0];
        cp[32] = accO[r][1];
    }

    // ---- dump band-packed P ----
    {
        float* dst = &g_P[((size_t)(b * HH + h) * LL + q0) * BAND];
        const float4* src4 = (const float4*)sS;
        float4* dst4 = (float4*)dst;
        for (int idx = t; idx < QT * BAND / 4; idx += 256) dst4[idx] = src4[idx];
    }
}

// =====================================================================
// attn_weights[b,i,j] = mean_h P ; zeros outside band
// =====================================================================
__global__ __launch_bounds__(256)
void attn_mean_kernel(float* __restrict__ aw)
{
    const int row = blockIdx.x;          // b*L + i
    const int b = row >> 10;
    const int i = row & (LL - 1);
    const int qt0 = (i >> 5) << 5;
    const int j0 = qt0 - WW;
    for (int j = threadIdx.x; j < LL; j += 256) {
        float v = 0.f;
        const int jj = j - j0;
        if (j >= i - WW && j <= i + WW) {
#pragma unroll
            for (int h = 0; h < HH; h++)
                v += g_P[((size_t)(b * HH + h) * LL + i) * BAND + jj];
            v *= (1.0f / HH);
        }
        aw[(size_t)row * LL + j] = v;
    }
}

// =====================================================================
// LayerNorm over last dim (1024). One block per row.
// =====================================================================
__global__ __launch_bounds__(256)
void ln_kernel(const float* __restrict__ in, const float* __restrict__ g,
               const float* __restrict__ bta, float* __restrict__ out)
{
    const int row = blockIdx.x;
    const int t = threadIdx.x;
    const float4 v = ((const float4*)(in + (size_t)row * EE))[t];
    float s  = v.x + v.y + v.z + v.w;
    float s2 = v.x * v.x + v.y * v.y + v.z * v.z + v.w * v.w;
#pragma unroll
    for (int off = 16; off > 0; off >>= 1) {
        s  += __shfl_xor_sync(0xffffffffu, s, off);
        s2 += __shfl_xor_sync(0xffffffffu, s2, off);
    }
    __shared__ float sa[8], sb[8];
    __shared__ float s_mu, s_inv;
    const int w = t >> 5, lane = t & 31;
    if (lane == 0) { sa[w] = s; sb[w] = s2; }
    __syncthreads();
    if (t == 0) {
        float S = 0.f, S2 = 0.f;
#pragma unroll
        for (int k = 0; k < 8; k++) { S += sa[k]; S2 += sb[k]; }
        const float mu = S / (float)EE;
        const float var = S2 / (float)EE - mu * mu;
        s_mu = mu;
        s_inv = rsqrtf(var + 1e-5f);
    }
    __syncthreads();
    const float mu = s_mu, inv = s_inv;
    const float4 gg = ((const float4*)g)[t];
    const float4 bb = ((const float4*)bta)[t];
    float4 o;
    o.x = (v.x - mu) * inv * gg.x + bb.x;
    o.y = (v.y - mu) * inv * gg.y + bb.y;
    o.z = (v.z - mu) * inv * gg.z + bb.z;
    o.w = (v.w - mu) * inv * gg.w + bb.w;
    ((float4*)(out + (size_t)row * EE))[t] = o;
}

// =====================================================================
extern "C" void kernel_launch(void* const* d_in, const int* in_sizes, int n_in,
                              void* d_out, int out_size)
{
    (void)in_sizes; (void)n_in; (void)out_size;
    const float* x          = (const float*)d_in[0];
    const float* in_proj_w  = (const float*)d_in[1];
    const float* in_proj_b  = (const float*)d_in[2];
    const float* out_proj_w = (const float*)d_in[3];
    const float* out_proj_b = (const float*)d_in[4];
    const float* ln1_g      = (const float*)d_in[5];
    const float* ln1_b      = (const float*)d_in[6];
    const float* w1         = (const float*)d_in[7];
    const float* b1         = (const float*)d_in[8];
    const float* w2         = (const float*)d_in[9];
    const float* b2         = (const float*)d_in[10];
    const float* ln2_g      = (const float*)d_in[11];
    const float* ln2_b      = (const float*)d_in[12];

    float* out = (float*)d_out;
    float* aw  = out + (size_t)BB * LL * EE;

    float *p_qkv, *p_ctx, *p_s1, *p_h, *p_ff, *p_s2;
    cudaGetSymbolAddress((void**)&p_qkv, g_qkv);
    cudaGetSymbolAddress((void**)&p_ctx, g_ctx);
    cudaGetSymbolAddress((void**)&p_s1,  g_s1);
    cudaGetSymbolAddress((void**)&p_h,   g_h);
    cudaGetSymbolAddress((void**)&p_ff,  g_ff);
    cudaGetSymbolAddress((void**)&p_s2,  g_s2);

    const int ATTN_SMEM = (QT * DP + 2 * BAND * DP + QT * BAND) * (int)sizeof(float);
    cudaFuncSetAttribute(attn_kernel, cudaFuncAttributeMaxDynamicSharedMemorySize, ATTN_SMEM);

    // 1. QKV projection: [4096,3072] = x @ in_proj_w^T + b
    gemm_tn<<<dim3(E3 / BN, NT / BM), 256>>>(x, in_proj_w, in_proj_b, nullptr,
                                             p_qkv, NT, E3, EE, 0);
    // 2. banded attention
    attn_kernel<<<dim3(LL / QT, HH, BB), 256, ATTN_SMEM>>>(p_qkv);
    // 3. head-mean attention weights
    attn_mean_kernel<<<NT, 256>>>(aw);
    // 4. out_proj + residual(x)
    gemm_tn<<<dim3(EE / BN, NT / BM), 256>>>(p_ctx, out_proj_w, out_proj_b, x,
                                             p_s1, NT, EE, EE, 0);
    // 5. LN1
    ln_kernel<<<NT, 256>>>(p_s1, ln1_g, ln1_b, p_h);
    // 6. FFN1 + relu
    gemm_tn<<<dim3(E4 / BN, NT / BM), 256>>>(p_h, w1, b1, nullptr,
                                             p_ff, NT, E4, EE, 1);
    // 7. FFN2 + residual(h)
    gemm_tn<<<dim3(EE / BN, NT / BM), 256>>>(p_ff, w2, b2, p_h,
                                             p_s2, NT, EE, E4, 0);
    // 8. LN2 -> out
    ln_kernel<<<NT, 256>>>(p_s2, ln2_g, ln2_b, out);
}

// round 2
// speedup vs baseline: 1.0137x; 1.0137x over previous
#include <cuda_runtime.h>
#include <cuda_bf16.h>
#include <math.h>

// Problem constants (fixed by setup_inputs)
#define BB   4
#define LL   1024
#define EE   1024
#define HH   16
#define DD   64
#define WW   128
#define NT   (BB*LL)          // 4096 rows
#define E3   (3*EE)
#define E4   (4*EE)

#define QT   32               // queries per attention block
#define BAND (QT + 2*WW)      // 288
#define KP   68               // padded row stride (floats) for Q/K smem
#define VP   64               // V row stride (unpadded, 256B rows)

// ---------------- scratch (device globals; no allocation allowed) -------------
__device__ float g_qkv[NT * E3];          // 50 MB
__device__ float g_ctx[NT * EE];          // 16.8 MB
__device__ float g_s1 [NT * EE];          // x + attn_out
__device__ float g_h  [NT * EE];          // LN1 output
__device__ float g_ff [NT * E4];          // 67 MB
__device__ float g_s2 [NT * EE];          // h + ff
__device__ float g_P  [BB * HH * LL * BAND];  // 75.5 MB band-packed probs

// =====================================================================
// GEMM:  C[M,N] = A[M,K] * W[N,K]^T + bias[N] (+ res[M,N]) (relu optional)
// 128x128 block tile, BK=16, 256 threads, 8x8 per thread.
// =====================================================================
#define BM 128
#define BN 128
#define BK 16
#define SPAD 4

__global__ __launch_bounds__(256, 2)
void gemm_tn(const float* __restrict__ A, const float* __restrict__ W,
             const float* __restrict__ bias, const float* __restrict__ res,
             float* __restrict__ C, int M, int N, int K, int relu)
{
    __shared__ float As[BK][BM + SPAD];
    __shared__ float Bs[BK][BN + SPAD];

    const int t  = threadIdx.x;
    const int tx = t & 15;          // 0..15  (cols)
    const int ty = t >> 4;          // 0..15  (rows)
    const int m0 = blockIdx.y * BM;
    const int n0 = blockIdx.x * BN;

    const int lrow = t >> 2;        // 0..63
    const int lk4  = (t & 3) * 4;   // 0,4,8,12

    float acc[8][8];
#pragma unroll
    for (int i = 0; i < 8; i++)
#pragma unroll
        for (int j = 0; j < 8; j++) acc[i][j] = 0.f;

    for (int k0 = 0; k0 < K; k0 += BK) {
        const float4 av0 = *(const float4*)&A[(size_t)(m0 + lrow)      * K + k0 + lk4];
        const float4 av1 = *(const float4*)&A[(size_t)(m0 + lrow + 64) * K + k0 + lk4];
        const float4 bv0 = *(const float4*)&W[(size_t)(n0 + lrow)      * K + k0 + lk4];
        const float4 bv1 = *(const float4*)&W[(size_t)(n0 + lrow + 64) * K + k0 + lk4];
        __syncthreads();
        As[lk4 + 0][lrow] = av0.x; As[lk4 + 1][lrow] = av0.y;
        As[lk4 + 2][lrow] = av0.z; As[lk4 + 3][lrow] = av0.w;
        As[lk4 + 0][lrow + 64] = av1.x; As[lk4 + 1][lrow + 64] = av1.y;
        As[lk4 + 2][lrow + 64] = av1.z; As[lk4 + 3][lrow + 64] = av1.w;
        Bs[lk4 + 0][lrow] = bv0.x; Bs[lk4 + 1][lrow] = bv0.y;
        Bs[lk4 + 2][lrow] = bv0.z; Bs[lk4 + 3][lrow] = bv0.w;
        Bs[lk4 + 0][lrow + 64] = bv1.x; Bs[lk4 + 1][lrow + 64] = bv1.y;
        Bs[lk4 + 2][lrow + 64] = bv1.z; Bs[lk4 + 3][lrow + 64] = bv1.w;
        __syncthreads();

#pragma unroll
        for (int kk = 0; kk < BK; kk++) {
            float4 a0 = *(const float4*)&As[kk][ty * 8];
            float4 a1 = *(const float4*)&As[kk][ty * 8 + 4];
            float4 b0 = *(const float4*)&Bs[kk][tx * 8];
            float4 b1 = *(const float4*)&Bs[kk][tx * 8 + 4];
            float a[8] = {a0.x, a0.y, a0.z, a0.w, a1.x, a1.y, a1.z, a1.w};
            float b[8] = {b0.x, b0.y, b0.z, b0.w, b1.x, b1.y, b1.z, b1.w};
#pragma unroll
            for (int i = 0; i < 8; i++)
#pragma unroll
                for (int j = 0; j < 8; j++)
                    acc[i][j] = fmaf(a[i], b[j], acc[i][j]);
        }
    }

    // epilogue
    const float4 bz0 = *(const float4*)&bias[n0 + tx * 8];
    const float4 bz1 = *(const float4*)&bias[n0 + tx * 8 + 4];
    const float bvec[8] = {bz0.x, bz0.y, bz0.z, bz0.w, bz1.x, bz1.y, bz1.z, bz1.w};
#pragma unroll
    for (int i = 0; i < 8; i++) {
        const int m = m0 + ty * 8 + i;
        float v[8];
#pragma unroll
        for (int j = 0; j < 8; j++) v[j] = acc[i][j] + bvec[j];
        if (res) {
            const float4 r0 = *(const float4*)&res[(size_t)m * N + n0 + tx * 8];
            const float4 r1 = *(const float4*)&res[(size_t)m * N + n0 + tx * 8 + 4];
            v[0] += r0.x; v[1] += r0.y; v[2] += r0.z; v[3] += r0.w;
            v[4] += r1.x; v[5] += r1.y; v[6] += r1.z; v[7] += r1.w;
        }
        if (relu) {
#pragma unroll
            for (int j = 0; j < 8; j++) v[j] = fmaxf(v[j], 0.f);
        }
        *(float4*)&C[(size_t)m * N + n0 + tx * 8]     = make_float4(v[0], v[1], v[2], v[3]);
        *(float4*)&C[(size_t)m * N + n0 + tx * 8 + 4] = make_float4(v[4], v[5], v[6], v[7]);
    }
}

// =====================================================================
// Banded attention: one block per (b, head, 32-query tile).
// Full band (288 keys) in smem -> exact softmax, then P@V.
// Vectorized (float4 LDS) with register tiling to avoid crossbar bound.
// =====================================================================
__global__ __launch_bounds__(256, 1)
void attn_kernel(const float* __restrict__ qkv)
{
    extern __shared__ float sm[];
    float* sQ = sm;                         // QT * KP    (2176)
    float* sK = sQ + QT * KP;               // BAND * KP  (19584)
    float* sV = sK + BAND * KP;             // BAND * VP  (18432)
    float* sS = sV + BAND * VP;             // QT * BAND  (9216)

    const int t  = threadIdx.x;
    const int qtile = blockIdx.x;
    const int h  = blockIdx.y;
    const int b  = blockIdx.z;
    const int q0 = qtile * QT;
    const int j0 = q0 - WW;

    // ---- load Q (32 x 64) ----
    for (int idx = t; idx < QT * 16; idx += 256) {
        const int row = idx >> 4, c4 = (idx & 15) * 4;
        const float4 q4 = *(const float4*)&qkv[(size_t)(b * LL + q0 + row) * E3 + h * DD + c4];
        *(float4*)&sQ[row * KP + c4] = q4;
    }
    // ---- load K, V band (288 x 64), zero-fill out of range ----
    for (int idx = t; idx < BAND * 16; idx += 256) {
        const int row = idx >> 4, c4 = (idx & 15) * 4;
        const int j = j0 + row;
        float4 k4 = make_float4(0.f, 0.f, 0.f, 0.f);
        float4 v4 = k4;
        if (j >= 0 && j < LL) {
            const float* kp = &qkv[(size_t)(b * LL + j) * E3 + EE + h * DD + c4];
            k4 = *(const float4*)kp;
            v4 = *(const float4*)(kp + EE);
        }
        *(float4*)&sK[row * KP + c4] = k4;
        *(float4*)&sV[row * VP + c4] = v4;
    }
    __syncthreads();

    const int tx = t & 31;   // 0..31
    const int ty = t >> 5;   // 0..7

    // ---- S = Q K^T * 1/8, masked.  thread: 4 rows x 9 cols, d vectorized ----
    float accS[4][9];
#pragma unroll
    for (int r = 0; r < 4; r++)
#pragma unroll
        for (int c = 0; c < 9; c++) accS[r][c] = 0.f;

#pragma unroll 4
    for (int d4 = 0; d4 < 16; d4++) {
        float4 q4[4];
#pragma unroll
        for (int r = 0; r < 4; r++)
            q4[r] = *(const float4*)&sQ[(ty + 8 * r) * KP + d4 * 4];
#pragma unroll
        for (int c = 0; c < 9; c++) {
            const float4 k4 = *(const float4*)&sK[(tx + 32 * c) * KP + d4 * 4];
#pragma unroll
            for (int r = 0; r < 4; r++) {
                accS[r][c] = fmaf(q4[r].x, k4.x, accS[r][c]);
                accS[r][c] = fmaf(q4[r].y, k4.y, accS[r][c]);
                accS[r][c] = fmaf(q4[r].z, k4.z, accS[r][c]);
                accS[r][c] = fmaf(q4[r].w, k4.w, accS[r][c]);
            }
        }
    }
#pragma unroll
    for (int r = 0; r < 4; r++) {
        const int qi = ty + 8 * r;
#pragma unroll
        for (int c = 0; c < 9; c++) {
            const int jj = tx + 32 * c;
            const int j = j0 + jj;
            const bool valid = (jj >= qi) && (jj <= qi + 2 * WW) && (j >= 0) && (j < LL);
            sS[qi * BAND + jj] = valid ? accS[r][c] * 0.125f : -1e30f;
        }
    }
    __syncthreads();

    // ---- softmax: warp w handles rows 4w..4w+3 ----
    {
        const int w = ty, lane = tx;
#pragma unroll
        for (int r = 0; r < 4; r++) {
            const int row = w * 4 + r;
            float vals[9];
            float mx = -1e30f;
#pragma unroll
            for (int c = 0; c < 9; c++) {
                vals[c] = sS[row * BAND + lane + 32 * c];
                mx = fmaxf(mx, vals[c]);
            }
#pragma unroll
            for (int off = 16; off > 0; off >>= 1)
                mx = fmaxf(mx, __shfl_xor_sync(0xffffffffu, mx, off));
            float s = 0.f;
#pragma unroll
            for (int c = 0; c < 9; c++) { vals[c] = __expf(vals[c] - mx); s += vals[c]; }
#pragma unroll
            for (int off = 16; off > 0; off >>= 1)
                s += __shfl_xor_sync(0xffffffffu, s, off);
            const float inv = 1.f / s;
#pragma unroll
            for (int c = 0; c < 9; c++)
                sS[row * BAND + lane + 32 * c] = vals[c] * inv;
        }
    }
    __syncthreads();

    // ---- ctx = P @ V.  thread: 4 rows x 1 float4 col-chunk, jj split by lane bit4 ----
    // lane layout: c = lane & 15 (float4 chunk, 16 chunks = 64 cols),
    //              jpar = lane >> 4 (handles jj%8 in {4*jpar .. 4*jpar+3})
    // 8-lane LDS groups read one contiguous 128B half-row of V -> 1 phase.
    {
        const int rg   = ty;          // row group: rows rg, rg+8, rg+16, rg+24
        const int c    = tx & 15;     // col chunk
        const int jpar = tx >> 4;     // 0/1

        float4 accO[4];
#pragma unroll
        for (int r = 0; r < 4; r++) accO[r] = make_float4(0.f, 0.f, 0.f, 0.f);

#pragma unroll 2
        for (int jb = 0; jb < BAND; jb += 8) {
            float4 p4[4];
#pragma unroll
            for (int r = 0; r < 4; r++)
                p4[r] = *(const float4*)&sS[(rg + 8 * r) * BAND + jb + 4 * jpar];
            const float pv[4][4] = {
                {p4[0].x, p4[0].y, p4[0].z, p4[0].w},
                {p4[1].x, p4[1].y, p4[1].z, p4[1].w},
                {p4[2].x, p4[2].y, p4[2].z, p4[2].w},
                {p4[3].x, p4[3].y, p4[3].z, p4[3].w}};
#pragma unroll
            for (int i = 0; i < 4; i++) {
                const float4 v4 = *(const float4*)&sV[(jb + 4 * jpar + i) * VP + c * 4];
#pragma unroll
                for (int r = 0; r < 4; r++) {
                    accO[r].x = fmaf(pv[r][i], v4.x, accO[r].x);
                    accO[r].y = fmaf(pv[r][i], v4.y, accO[r].y);
                    accO[r].z = fmaf(pv[r][i], v4.z, accO[r].z);
                    accO[r].w = fmaf(pv[r][i], v4.w, accO[r].w);
                }
            }
        }
        // reduce across jpar (lane bit 4)
#pragma unroll
        for (int r = 0; r < 4; r++) {
            accO[r].x += __shfl_xor_sync(0xffffffffu, accO[r].x, 16);
            accO[r].y += __shfl_xor_sync(0xffffffffu, accO[r].y, 16);
            accO[r].z += __shfl_xor_sync(0xffffffffu, accO[r].z, 16);
            accO[r].w += __shfl_xor_sync(0xffffffffu, accO[r].w, 16);
        }
        if (jpar == 0) {
#pragma unroll
            for (int r = 0; r < 4; r++) {
                const int qi = rg + 8 * r;
                *(float4*)&g_ctx[(size_t)(b * LL + q0 + qi) * EE + h * DD + c * 4] = accO[r];
            }
        }
    }

    // ---- dump band-packed P ----
    {
        float* dst = &g_P[((size_t)(b * HH + h) * LL + q0) * BAND];
        const float4* src4 = (const float4*)sS;
        float4* dst4 = (float4*)dst;
        for (int idx = t; idx < QT * BAND / 4; idx += 256) dst4[idx] = src4[idx];
    }
}

// =====================================================================
// attn_weights[b,i,j] = mean_h P ; zeros outside band
// =====================================================================
__global__ __launch_bounds__(256)
void attn_mean_kernel(float* __restrict__ aw)
{
    const int row = blockIdx.x;          // b*L + i
    const int b = row >> 10;
    const int i = row & (LL - 1);
    const int qt0 = (i >> 5) << 5;
    const int j0 = qt0 - WW;
    for (int j = threadIdx.x; j < LL; j += 256) {
        float v = 0.f;
        const int jj = j - j0;
        if (j >= i - WW && j <= i + WW) {
#pragma unroll
            for (int h = 0; h < HH; h++)
                v += g_P[((size_t)(b * HH + h) * LL + i) * BAND + jj];
            v *= (1.0f / HH);
        }
        aw[(size_t)row * LL + j] = v;
    }
}

// =====================================================================
// LayerNorm over last dim (1024). One block per row.
// =====================================================================
__global__ __launch_bounds__(256)
void ln_kernel(const float* __restrict__ in, const float* __restrict__ g,
               const float* __restrict__ bta, float* __restrict__ out)
{
    const int row = blockIdx.x;
    const int t = threadIdx.x;
    const float4 v = ((const float4*)(in + (size_t)row * EE))[t];
    float s  = v.x + v.y + v.z + v.w;
    float s2 = v.x * v.x + v.y * v.y + v.z * v.z + v.w * v.w;
#pragma unroll
    for (int off = 16; off > 0; off >>= 1) {
        s  += __shfl_xor_sync(0xffffffffu, s, off);
        s2 += __shfl_xor_sync(0xffffffffu, s2, off);
    }
    __shared__ float sa[8], sb[8];
    __shared__ float s_mu, s_inv;
    const int w = t >> 5, lane = t & 31;
    if (lane == 0) { sa[w] = s; sb[w] = s2; }
    __syncthreads();
    if (t == 0) {
        float S = 0.f, S2 = 0.f;
#pragma unroll
        for (int k = 0; k < 8; k++) { S += sa[k]; S2 += sb[k]; }
        const float mu = S / (float)EE;
        const float var = S2 / (float)EE - mu * mu;
        s_mu = mu;
        s_inv = rsqrtf(var + 1e-5f);
    }
    __syncthreads();
    const float mu = s_mu, inv = s_inv;
    const float4 gg = ((const float4*)g)[t];
    const float4 bb = ((const float4*)bta)[t];
    float4 o;
    o.x = (v.x - mu) * inv * gg.x + bb.x;
    o.y = (v.y - mu) * inv * gg.y + bb.y;
    o.z = (v.z - mu) * inv * gg.z + bb.z;
    o.w = (v.w - mu) * inv * gg.w + bb.w;
    ((float4*)(out + (size_t)row * EE))[t] = o;
}

// =====================================================================
extern "C" void kernel_launch(void* const* d_in, const int* in_sizes, int n_in,
                              void* d_out, int out_size)
{
    (void)in_sizes; (void)n_in; (void)out_size;
    const float* x          = (const float*)d_in[0];
    const float* in_proj_w  = (const float*)d_in[1];
    const float* in_proj_b  = (const float*)d_in[2];
    const float* out_proj_w = (const float*)d_in[3];
    const float* out_proj_b = (const float*)d_in[4];
    const float* ln1_g      = (const float*)d_in[5];
    const float* ln1_b      = (const float*)d_in[6];
    const float* w1         = (const float*)d_in[7];
    const float* b1         = (const float*)d_in[8];
    const float* w2         = (const float*)d_in[9];
    const float* b2         = (const float*)d_in[10];
    const float* ln2_g      = (const float*)d_in[11];
    const float* ln2_b      = (const float*)d_in[12];

    float* out = (float*)d_out;
    float* aw  = out + (size_t)BB * LL * EE;

    float *p_qkv, *p_ctx, *p_s1, *p_h, *p_ff, *p_s2;
    cudaGetSymbolAddress((void**)&p_qkv, g_qkv);
    cudaGetSymbolAddress((void**)&p_ctx, g_ctx);
    cudaGetSymbolAddress((void**)&p_s1,  g_s1);
    cudaGetSymbolAddress((void**)&p_h,   g_h);
    cudaGetSymbolAddress((void**)&p_ff,  g_ff);
    cudaGetSymbolAddress((void**)&p_s2,  g_s2);

    const int ATTN_SMEM = (QT * KP + BAND * KP + BAND * VP + QT * BAND) * (int)sizeof(float);
    cudaFuncSetAttribute(attn_kernel, cudaFuncAttributeMaxDynamicSharedMemorySize, ATTN_SMEM);

    // 1. QKV projection: [4096,3072] = x @ in_proj_w^T + b
    gemm_tn<<<dim3(E3 / BN, NT / BM), 256>>>(x, in_proj_w, in_proj_b, nullptr,
                                             p_qkv, NT, E3, EE, 0);
    // 2. banded attention
    attn_kernel<<<dim3(LL / QT, HH, BB), 256, ATTN_SMEM>>>(p_qkv);
    // 3. head-mean attention weights
    attn_mean_kernel<<<NT, 256>>>(aw);
    // 4. out_proj + residual(x)
    gemm_tn<<<dim3(EE / BN, NT / BM), 256>>>(p_ctx, out_proj_w, out_proj_b, x,
                                             p_s1, NT, EE, EE, 0);
    // 5. LN1
    ln_kernel<<<NT, 256>>>(p_s1, ln1_g, ln1_b, p_h);
    // 6. FFN1 + relu
    gemm_tn<<<dim3(E4 / BN, NT / BM), 256>>>(p_h, w1, b1, nullptr,
                                             p_ff, NT, E4, EE, 1);
    // 7. FFN2 + residual(h)
    gemm_tn<<<dim3(EE / BN, NT / BM), 256>>>(p_ff, w2, b2, p_h,
                                             p_s2, NT, EE, E4, 0);
    // 8. LN2 -> out
    ln_kernel<<<NT, 256>>>(p_s2, ln2_g, ln2_b, out);
}

// round 4
// speedup vs baseline: 2.5933x; 2.5584x over previous
#include <cuda_runtime.h>
#include <cuda_bf16.h>
#include <math.h>
#include <stdint.h>

// Problem constants (fixed by setup_inputs)
#define BB   4
#define LL   1024
#define EE   1024
#define HH   16
#define DD   64
#define WW   128
#define NT   (BB*LL)          // 4096 rows
#define E3   (3*EE)
#define E4   (4*EE)

#define QT   32               // queries per attention block
#define BAND (QT + 2*WW)      // 288
#define KP   68               // padded row stride (floats) for Q/K smem
#define VP   64               // V row stride

// ---------------- scratch (device globals; no allocation allowed) -------------
__device__ float g_qkv[NT * E3];
__device__ float g_ctx[NT * EE];          // tf32-rounded ctx (feeds out_proj)
__device__ float g_s1 [NT * EE];
__device__ float g_h  [NT * EE];          // LN1 out fp32 (residual for FFN2)
__device__ float g_htf[NT * EE];          // LN1 out tf32-rounded (FFN1 A)
__device__ float g_ff [NT * E4];          // FFN1 out (tf32-rounded, FFN2 A)
__device__ float g_s2 [NT * EE];
__device__ float g_xtf[NT * EE];          // x tf32-rounded (QKV A)
__device__ float g_wtf[(size_t)E3*EE + (size_t)EE*EE + (size_t)E4*EE + (size_t)EE*E4];
__device__ float g_P  [BB * HH * LL * BAND];

#define WQ_OFF 0
#define WO_OFF ((size_t)E3*EE)
#define W1_OFF (WO_OFF + (size_t)EE*EE)
#define W2_OFF (W1_OFF + (size_t)E4*EE)

// ============================ helpers =============================
__device__ __forceinline__ uint32_t smem_u32(const void* p) {
    uint32_t a;
    asm("{ .reg .u64 t; cvta.to.shared.u64 t, %1; cvt.u32.u64 %0, t; }" : "=r"(a) : "l"(p));
    return a;
}
__device__ __forceinline__ float tf32r(float x) {
    uint32_t u;
    asm("cvt.rna.tf32.f32 %0, %1;" : "=r"(u) : "f"(x));
    return __uint_as_float(u);
}

#define CP_ASYNC16(dst, src) \
    asm volatile("cp.async.cg.shared.global [%0], [%1], 16;" :: "r"(dst), "l"(src) : "memory")
#define CP_COMMIT() asm volatile("cp.async.commit_group;" ::: "memory")

__device__ __forceinline__ void mma_tf32(float& d0, float& d1, float& d2, float& d3,
                                         uint32_t a0, uint32_t a1, uint32_t a2, uint32_t a3,
                                         uint32_t b0, uint32_t b1) {
    asm volatile(
        "mma.sync.aligned.m16n8k8.row.col.f32.tf32.tf32.f32 "
        "{%0,%1,%2,%3}, {%4,%5,%6,%7}, {%8,%9}, {%0,%1,%2,%3};"
        : "+f"(d0), "+f"(d1), "+f"(d2), "+f"(d3)
        : "r"(a0), "r"(a1), "r"(a2), "r"(a3), "r"(b0), "r"(b1));
}

// =====================================================================
// tf32 mma.sync GEMM: C[M,N] = A[M,K] * W[N,K]^T + bias (+res)(relu)(round)
// 128x128 CTA tile, BK=16, 3-stage cp.async, 4 warps (64x64 each).
// mode bit0 = relu, bit1 = round output to tf32.
// A and W must be tf32-rounded already. M,N multiples of 128; K mult of 16.
// =====================================================================
#define APITCH 20                 // floats per smem row (16 + 4 pad)
#define ATILE  (128 * APITCH)     // 2560 floats per matrix per stage
#define STAGEF (2 * ATILE)        // 5120 floats = 20480 B per stage
#define GSMEM_DYN (3 * STAGEF * 4)

__global__ __launch_bounds__(128)
void gemm_mma(const float* __restrict__ A, const float* __restrict__ W,
              const float* __restrict__ bias, const float* __restrict__ res,
              float* __restrict__ C, int M, int N, int K, int mode)
{
    extern __shared__ float sh[];
    const uint32_t shb = smem_u32(sh);

    const int tid   = threadIdx.x;
    const int warp  = tid >> 5;
    const int lane  = tid & 31;
    const int g     = lane >> 2;          // group id (0..7)
    const int t4    = lane & 3;           // thread in group (0..3)
    const int warpM = (warp >> 1) * 64;   // 0 or 64
    const int warpN = (warp & 1) * 64;    // 0 or 64
    const int m0 = blockIdx.y * 128;
    const int n0 = blockIdx.x * 128;

    const int nk = K >> 4;

    float acc[4][8][4];
#pragma unroll
    for (int mt = 0; mt < 4; mt++)
#pragma unroll
        for (int nt = 0; nt < 8; nt++)
#pragma unroll
            for (int q = 0; q < 4; q++) acc[mt][nt][q] = 0.f;

    // ---- async stage loader: 1024 x 16B chunks, 8 per thread ----
#define LOAD_STAGE(kb, s) do {                                               \
        const uint32_t sbase = shb + (uint32_t)(s) * (STAGEF * 4);           \
        _Pragma("unroll")                                                    \
        for (int i = 0; i < 8; i++) {                                        \
            const int idx = tid + i * 128;        /* 0..1023 */              \
            const int mat = idx >> 9;             /* 0 = A, 1 = B */         \
            const int r   = (idx >> 2) & 127;                                \
            const int c   = idx & 3;                                         \
            const float* src = (mat ? (W + (size_t)(n0 + r) * K)             \
                                    : (A + (size_t)(m0 + r) * K))            \
                               + (size_t)(kb) * 16 + c * 4;                  \
            const uint32_t dst = sbase + (uint32_t)(mat * (ATILE * 4)        \
                               + r * (APITCH * 4) + c * 16);                 \
            CP_ASYNC16(dst, src);                                            \
        }                                                                    \
        CP_COMMIT();                                                         \
    } while (0)

    LOAD_STAGE(0, 0);
    LOAD_STAGE(1, 1);

    for (int kb = 0; kb < nk; kb++) {
        if (kb + 2 < nk) LOAD_STAGE(kb + 2, (kb + 2) % 3);
        const int n_after = (nk - 1 - kb) < 2 ? (nk - 1 - kb) : 2;
        if (n_after == 2)      asm volatile("cp.async.wait_group 2;" ::: "memory");
        else if (n_after == 1) asm volatile("cp.async.wait_group 1;" ::: "memory");
        else                   asm volatile("cp.async.wait_group 0;" ::: "memory");
        __syncthreads();

        const float* As = sh + (kb % 3) * STAGEF;
        const float* Bs = As + ATILE;
#pragma unroll
        for (int ks = 0; ks < 2; ks++) {
            uint32_t af[4][4];
#pragma unroll
            for (int mt = 0; mt < 4; mt++) {
                const float* ap = As + (warpM + mt * 16 + g) * APITCH + ks * 8 + t4;
                af[mt][0] = __float_as_uint(ap[0]);
                af[mt][1] = __float_as_uint(ap[8 * APITCH]);
                af[mt][2] = __float_as_uint(ap[4]);
                af[mt][3] = __float_as_uint(ap[8 * APITCH + 4]);
            }
            uint32_t bf[8][2];
#pragma unroll
            for (int nt = 0; nt < 8; nt++) {
                const float* bp = Bs + (warpN + nt * 8 + g) * APITCH + ks * 8 + t4;
                bf[nt][0] = __float_as_uint(bp[0]);
                bf[nt][1] = __float_as_uint(bp[4]);
            }
#pragma unroll
            for (int mt = 0; mt < 4; mt++)
#pragma unroll
                for (int nt = 0; nt < 8; nt++)
                    mma_tf32(acc[mt][nt][0], acc[mt][nt][1], acc[mt][nt][2], acc[mt][nt][3],
                             af[mt][0], af[mt][1], af[mt][2], af[mt][3],
                             bf[nt][0], bf[nt][1]);
        }
        __syncthreads();
    }

    // ---- epilogue ----
    const bool do_relu  = (mode & 1) != 0;
    const bool do_round = (mode & 2) != 0;
#pragma unroll
    for (int mt = 0; mt < 4; mt++) {
        const int row0 = m0 + warpM + mt * 16 + g;
        const int row1 = row0 + 8;
#pragma unroll
        for (int nt = 0; nt < 8; nt++) {
            const int col = n0 + warpN + nt * 8 + 2 * t4;
            const float2 bz = *(const float2*)&bias[col];
            float2 u, v;
            u.x = acc[mt][nt][0] + bz.x;  u.y = acc[mt][nt][1] + bz.y;
            v.x = acc[mt][nt][2] + bz.x;  v.y = acc[mt][nt][3] + bz.y;
            if (res) {
                const float2 r0 = *(const float2*)&res[(size_t)row0 * N + col];
                const float2 r1 = *(const float2*)&res[(size_t)row1 * N + col];
                u.x += r0.x; u.y += r0.y; v.x += r1.x; v.y += r1.y;
            }
            if (do_relu) {
                u.x = fmaxf(u.x, 0.f); u.y = fmaxf(u.y, 0.f);
                v.x = fmaxf(v.x, 0.f); v.y = fmaxf(v.y, 0.f);
            }
            if (do_round) {
                u.x = tf32r(u.x); u.y = tf32r(u.y);
                v.x = tf32r(v.x); v.y = tf32r(v.y);
            }
            *(float2*)&C[(size_t)row0 * N + col] = u;
            *(float2*)&C[(size_t)row1 * N + col] = v;
        }
    }
#undef LOAD_STAGE
}

// =====================================================================
// round-to-tf32 copy kernel (float4 per thread)
// =====================================================================
__global__ __launch_bounds__(256)
void cvt_tf32_kernel(const float* __restrict__ in, float* __restrict__ out, int n4)
{
    const int i = blockIdx.x * 256 + threadIdx.x;
    if (i < n4) {
        float4 v = ((const float4*)in)[i];
        v.x = tf32r(v.x); v.y = tf32r(v.y); v.z = tf32r(v.z); v.w = tf32r(v.w);
        ((float4*)out)[i] = v;
    }
}

// =====================================================================
// Banded attention (validated round 1; ctx output tf32-rounded)
// =====================================================================
__global__ __launch_bounds__(256, 1)
void attn_kernel(const float* __restrict__ qkv)
{
    extern __shared__ float sm[];
    float* sQ = sm;
    float* sK = sQ + QT * KP;
    float* sV = sK + BAND * KP;
    float* sS = sV + BAND * VP;

    const int t  = threadIdx.x;
    const int qtile = blockIdx.x;
    const int h  = blockIdx.y;
    const int b  = blockIdx.z;
    const int q0 = qtile * QT;
    const int j0 = q0 - WW;

    for (int idx = t; idx < QT * 16; idx += 256) {
        const int row = idx >> 4, c4 = (idx & 15) * 4;
        const float4 q4 = *(const float4*)&qkv[(size_t)(b * LL + q0 + row) * E3 + h * DD + c4];
        *(float4*)&sQ[row * KP + c4] = q4;
    }
    for (int idx = t; idx < BAND * 16; idx += 256) {
        const int row = idx >> 4, c4 = (idx & 15) * 4;
        const int j = j0 + row;
        float4 k4 = make_float4(0.f, 0.f, 0.f, 0.f);
        float4 v4 = k4;
        if (j >= 0 && j < LL) {
            const float* kp = &qkv[(size_t)(b * LL + j) * E3 + EE + h * DD + c4];
            k4 = *(const float4*)kp;
            v4 = *(const float4*)(kp + EE);
        }
        *(float4*)&sK[row * KP + c4] = k4;
        *(float4*)&sV[row * VP + c4] = v4;
    }
    __syncthreads();

    const int tx = t & 31;
    const int ty = t >> 5;

    float accS[4][9];
#pragma unroll
    for (int r = 0; r < 4; r++)
#pragma unroll
        for (int c = 0; c < 9; c++) accS[r][c] = 0.f;

#pragma unroll 4
    for (int d4 = 0; d4 < 16; d4++) {
        float4 q4[4];
#pragma unroll
        for (int r = 0; r < 4; r++)
            q4[r] = *(const float4*)&sQ[(ty + 8 * r) * KP + d4 * 4];
#pragma unroll
        for (int c = 0; c < 9; c++) {
            const float4 k4 = *(const float4*)&sK[(tx + 32 * c) * KP + d4 * 4];
#pragma unroll
            for (int r = 0; r < 4; r++) {
                accS[r][c] = fmaf(q4[r].x, k4.x, accS[r][c]);
                accS[r][c] = fmaf(q4[r].y, k4.y, accS[r][c]);
                accS[r][c] = fmaf(q4[r].z, k4.z, accS[r][c]);
                accS[r][c] = fmaf(q4[r].w, k4.w, accS[r][c]);
            }
        }
    }
#pragma unroll
    for (int r = 0; r < 4; r++) {
        const int qi = ty + 8 * r;
#pragma unroll
        for (int c = 0; c < 9; c++) {
            const int jj = tx + 32 * c;
            const int j = j0 + jj;
            const bool valid = (jj >= qi) && (jj <= qi + 2 * WW) && (j >= 0) && (j < LL);
            sS[qi * BAND + jj] = valid ? accS[r][c] * 0.125f : -1e30f;
        }
    }
    __syncthreads();

    {
        const int w = ty, lane = tx;
#pragma unroll
        for (int r = 0; r < 4; r++) {
            const int row = w * 4 + r;
            float vals[9];
            float mx = -1e30f;
#pragma unroll
            for (int c = 0; c < 9; c++) {
                vals[c] = sS[row * BAND + lane + 32 * c];
                mx = fmaxf(mx, vals[c]);
            }
#pragma unroll
            for (int off = 16; off > 0; off >>= 1)
                mx = fmaxf(mx, __shfl_xor_sync(0xffffffffu, mx, off));
            float s = 0.f;
#pragma unroll
            for (int c = 0; c < 9; c++) { vals[c] = __expf(vals[c] - mx); s += vals[c]; }
#pragma unroll
            for (int off = 16; off > 0; off >>= 1)
                s += __shfl_xor_sync(0xffffffffu, s, off);
            const float inv = 1.f / s;
#pragma unroll
            for (int c = 0; c < 9; c++)
                sS[row * BAND + lane + 32 * c] = vals[c] * inv;
        }
    }
    __syncthreads();

    {
        const int rg   = ty;
        const int c    = tx & 15;
        const int jpar = tx >> 4;

        float4 accO[4];
#pragma unroll
        for (int r = 0; r < 4; r++) accO[r] = make_float4(0.f, 0.f, 0.f, 0.f);

#pragma unroll 2
        for (int jb = 0; jb < BAND; jb += 8) {
            float4 p4[4];
#pragma unroll
            for (int r = 0; r < 4; r++)
                p4[r] = *(const float4*)&sS[(rg + 8 * r) * BAND + jb + 4 * jpar];
            const float pv[4][4] = {
                {p4[0].x, p4[0].y, p4[0].z, p4[0].w},
                {p4[1].x, p4[1].y, p4[1].z, p4[1].w},
                {p4[2].x, p4[2].y, p4[2].z, p4[2].w},
                {p4[3].x, p4[3].y, p4[3].z, p4[3].w}};
#pragma unroll
            for (int i = 0; i < 4; i++) {
                const float4 v4 = *(const float4*)&sV[(jb + 4 * jpar + i) * VP + c * 4];
#pragma unroll
                for (int r = 0; r < 4; r++) {
                    accO[r].x = fmaf(pv[r][i], v4.x, accO[r].x);
                    accO[r].y = fmaf(pv[r][i], v4.y, accO[r].y);
                    accO[r].z = fmaf(pv[r][i], v4.z, accO[r].z);
                    accO[r].w = fmaf(pv[r][i], v4.w, accO[r].w);
                }
            }
        }
#pragma unroll
        for (int r = 0; r < 4; r++) {
            accO[r].x += __shfl_xor_sync(0xffffffffu, accO[r].x, 16);
            accO[r].y += __shfl_xor_sync(0xffffffffu, accO[r].y, 16);
            accO[r].z += __shfl_xor_sync(0xffffffffu, accO[r].z, 16);
            accO[r].w += __shfl_xor_sync(0xffffffffu, accO[r].w, 16);
        }
        if (jpar == 0) {
#pragma unroll
            for (int r = 0; r < 4; r++) {
                const int qi = rg + 8 * r;
                float4 o = accO[r];
                o.x = tf32r(o.x); o.y = tf32r(o.y); o.z = tf32r(o.z); o.w = tf32r(o.w);
                *(float4*)&g_ctx[(size_t)(b * LL + q0 + qi) * EE + h * DD + c * 4] = o;
            }
        }
    }

    {
        float* dst = &g_P[((size_t)(b * HH + h) * LL + q0) * BAND];
        const float4* src4 = (const float4*)sS;
        float4* dst4 = (float4*)dst;
        for (int idx = t; idx < QT * BAND / 4; idx += 256) dst4[idx] = src4[idx];
    }
}

// =====================================================================
__global__ __launch_bounds__(256)
void attn_mean_kernel(float* __restrict__ aw)
{
    const int row = blockIdx.x;
    const int b = row >> 10;
    const int i = row & (LL - 1);
    const int qt0 = (i >> 5) << 5;
    const int j0 = qt0 - WW;
    for (int j = threadIdx.x; j < LL; j += 256) {
        float v = 0.f;
        const int jj = j - j0;
        if (j >= i - WW && j <= i + WW) {
#pragma unroll
            for (int h = 0; h < HH; h++)
                v += g_P[((size_t)(b * HH + h) * LL + i) * BAND + jj];
            v *= (1.0f / HH);
        }
        aw[(size_t)row * LL + j] = v;
    }
}

// =====================================================================
// LayerNorm; optionally also writes tf32-rounded copy.
// =====================================================================
__global__ __launch_bounds__(256)
void ln_kernel(const float* __restrict__ in, const float* __restrict__ g,
               const float* __restrict__ bta, float* __restrict__ out,
               float* __restrict__ out_tf)
{
    const int row = blockIdx.x;
    const int t = threadIdx.x;
    const float4 v = ((const float4*)(in + (size_t)row * EE))[t];
    float s  = v.x + v.y + v.z + v.w;
    float s2 = v.x * v.x + v.y * v.y + v.z * v.z + v.w * v.w;
#pragma unroll
    for (int off = 16; off > 0; off >>= 1) {
        s  += __shfl_xor_sync(0xffffffffu, s, off);
        s2 += __shfl_xor_sync(0xffffffffu, s2, off);
    }
    __shared__ float sa[8], sb[8];
    __shared__ float s_mu, s_inv;
    const int w = t >> 5, lane = t & 31;
    if (lane == 0) { sa[w] = s; sb[w] = s2; }
    __syncthreads();
    if (t == 0) {
        float S = 0.f, S2 = 0.f;
#pragma unroll
        for (int k = 0; k < 8; k++) { S += sa[k]; S2 += sb[k]; }
        const float mu = S / (float)EE;
        const float var = S2 / (float)EE - mu * mu;
        s_mu = mu;
        s_inv = rsqrtf(var + 1e-5f);
    }
    __syncthreads();
    const float mu = s_mu, inv = s_inv;
    const float4 gg = ((const float4*)g)[t];
    const float4 bb = ((const float4*)bta)[t];
    float4 o;
    o.x = (v.x - mu) * inv * gg.x + bb.x;
    o.y = (v.y - mu) * inv * gg.y + bb.y;
    o.z = (v.z - mu) * inv * gg.z + bb.z;
    o.w = (v.w - mu) * inv * gg.w + bb.w;
    ((float4*)(out + (size_t)row * EE))[t] = o;
    if (out_tf) {
        float4 o2;
        o2.x = tf32r(o.x); o2.y = tf32r(o.y); o2.z = tf32r(o.z); o2.w = tf32r(o.w);
        ((float4*)(out_tf + (size_t)row * EE))[t] = o2;
    }
}

// =====================================================================
extern "C" void kernel_launch(void* const* d_in, const int* in_sizes, int n_in,
                              void* d_out, int out_size)
{
    (void)in_sizes; (void)n_in; (void)out_size;
    const float* x          = (const float*)d_in[0];
    const float* in_proj_w  = (const float*)d_in[1];
    const float* in_proj_b  = (const float*)d_in[2];
    const float* out_proj_w = (const float*)d_in[3];
    const float* out_proj_b = (const float*)d_in[4];
    const float* ln1_g      = (const float*)d_in[5];
    const float* ln1_b      = (const float*)d_in[6];
    const float* w1         = (const float*)d_in[7];
    const float* b1         = (const float*)d_in[8];
    const float* w2         = (const float*)d_in[9];
    const float* b2         = (const float*)d_in[10];
    const float* ln2_g      = (const float*)d_in[11];
    const float* ln2_b      = (const float*)d_in[12];

    float* out = (float*)d_out;
    float* aw  = out + (size_t)BB * LL * EE;

    float *p_qkv, *p_ctx, *p_s1, *p_h, *p_htf, *p_ff, *p_s2, *p_xtf, *p_wtf;
    cudaGetSymbolAddress((void**)&p_qkv, g_qkv);
    cudaGetSymbolAddress((void**)&p_ctx, g_ctx);
    cudaGetSymbolAddress((void**)&p_s1,  g_s1);
    cudaGetSymbolAddress((void**)&p_h,   g_h);
    cudaGetSymbolAddress((void**)&p_htf, g_htf);
    cudaGetSymbolAddress((void**)&p_ff,  g_ff);
    cudaGetSymbolAddress((void**)&p_s2,  g_s2);
    cudaGetSymbolAddress((void**)&p_xtf, g_xtf);
    cudaGetSymbolAddress((void**)&p_wtf, g_wtf);

    const int ATTN_SMEM = (QT * KP + BAND * KP + BAND * VP + QT * BAND) * (int)sizeof(float);
    cudaFuncSetAttribute(attn_kernel, cudaFuncAttributeMaxDynamicSharedMemorySize, ATTN_SMEM);
    cudaFuncSetAttribute(gemm_mma, cudaFuncAttributeMaxDynamicSharedMemorySize, GSMEM_DYN);

    // 0. round inputs/weights to tf32 (RN) into scratch
    cvt_tf32_kernel<<<(NT * EE / 4 + 255) / 256, 256>>>(x, p_xtf, NT * EE / 4);
    cvt_tf32_kernel<<<(E3 * EE / 4 + 255) / 256, 256>>>(in_proj_w,  p_wtf + WQ_OFF, E3 * EE / 4);
    cvt_tf32_kernel<<<(EE * EE / 4 + 255) / 256, 256>>>(out_proj_w, p_wtf + WO_OFF, EE * EE / 4);
    cvt_tf32_kernel<<<(E4 * EE / 4 + 255) / 256, 256>>>(w1, p_wtf + W1_OFF, E4 * EE / 4);
    cvt_tf32_kernel<<<(EE * E4 / 4 + 255) / 256, 256>>>(w2, p_wtf + W2_OFF, EE * E4 / 4);

    // 1. QKV projection (tensor core tf32)
    gemm_mma<<<dim3(E3 / 128, NT / 128), 128, GSMEM_DYN>>>(
        p_xtf, p_wtf + WQ_OFF, in_proj_b, nullptr, p_qkv, NT, E3, EE, 0);
    // 2. banded attention (writes tf32-rounded ctx + band P)
    attn_kernel<<<dim3(LL / QT, HH, BB), 256, ATTN_SMEM>>>(p_qkv);
    // 3. head-mean attention weights
    attn_mean_kernel<<<NT, 256>>>(aw);
    // 4. out_proj + residual(x)
    gemm_mma<<<dim3(EE / 128, NT / 128), 128, GSMEM_DYN>>>(
        p_ctx, p_wtf + WO_OFF, out_proj_b, x, p_s1, NT, EE, EE, 0);
    // 5. LN1 -> h (fp32) + htf (tf32)
    ln_kernel<<<NT, 256>>>(p_s1, ln1_g, ln1_b, p_h, p_htf);
    // 6. FFN1 + relu, output rounded to tf32
    gemm_mma<<<dim3(E4 / 128, NT / 128), 128, GSMEM_DYN>>>(
        p_htf, p_wtf + W1_OFF, b1, nullptr, p_ff, NT, E4, EE, 3);
    // 7. FFN2 + residual(h)
    gemm_mma<<<dim3(EE / 128, NT / 128), 128, GSMEM_DYN>>>(
        p_ff, p_wtf + W2_OFF, b2, p_h, p_s2, NT, EE, E4, 0);
    // 8. LN2 -> out
    ln_kernel<<<NT, 256>>>(p_s2, ln2_g, ln2_b, out, nullptr);
}